// round 12
// baseline (speedup 1.0000x reference)
#include <cuda_runtime.h>
#include <stdint.h>

#define BETA      0.99f
#define T50       50
#define B_DIM     8192
#define IN_DIM    512
#define OUT_DIM   256

#define TILE_M    64          // batch rows per block
#define TILE_N    32          // output cols per block
#define BK        16
#define ROW_ELEMS (OUT_DIM * T50)   // 12800 floats per batch row

typedef unsigned long long ull;

__device__ __forceinline__ void fma2(ull& d, ull a, ull b) {
    asm("fma.rn.f32x2 %0, %1, %2, %0;" : "+l"(d) : "l"(a), "l"(b));
}
__device__ __forceinline__ ull dup2(float f) {
    ull r;
    asm("mov.b64 %0, {%1, %1};" : "=l"(r) : "f"(f));
    return r;
}

__global__ __launch_bounds__(128, 6) void snn_fused7(
    const float* __restrict__ x,     // [B_DIM, IN_DIM]
    const float* __restrict__ W,     // [OUT_DIM, IN_DIM]
    const float* __restrict__ bias,  // [OUT_DIM]
    float* __restrict__ out)         // [B_DIM, OUT_DIM, T50]
{
    __shared__ __align__(16) float As[BK][68];     // k-major, padded
    __shared__ __align__(16) ull   Bs2[BK][36];    // duplicated (b,b) per col
    __shared__ uint32_t s_msk[TILE_M * 16 * 4];    // 16 KB packed 100-bit streams

    const int tid  = threadIdx.x;
    const int tx   = tid & 7;           // col group (4 cols each -> 32)
    const int ty   = tid >> 3;          // row group (4 rows each -> 64)
    const int col0 = blockIdx.x * TILE_N;
    const int row0 = blockIdx.y * TILE_M;

    // ---------------- GEMM: cur = x @ W^T + b  (k strictly ascending) -------
    // M-paired f32x2 accumulators; each 64-bit half is an independent fma.rn
    // chain -> bit-identical currents to every passing round.
    ull acc64[8];
#pragma unroll
    for (int e = 0; e < 8; e++) acc64[e] = 0ull;

    const int lr = tid >> 2;            // 0..31
    const int lc = (tid & 3) << 2;      // 0,4,8,12
    const float* xp0 = x + (size_t)(row0 + lr) * IN_DIM + lc;
    const float* xp1 = xp0 + (size_t)32 * IN_DIM;
    const float* wp0 = W + (size_t)(col0 + lr) * IN_DIM + lc;

    float4 va0 = *reinterpret_cast<const float4*>(xp0);
    float4 va1 = *reinterpret_cast<const float4*>(xp1);
    float4 vb0 = *reinterpret_cast<const float4*>(wp0);

    for (int k0 = 0; k0 < IN_DIM; k0 += BK) {
        As[lc + 0][lr]      = va0.x; As[lc + 1][lr]      = va0.y;
        As[lc + 2][lr]      = va0.z; As[lc + 3][lr]      = va0.w;
        As[lc + 0][lr + 32] = va1.x; As[lc + 1][lr + 32] = va1.y;
        As[lc + 2][lr + 32] = va1.z; As[lc + 3][lr + 32] = va1.w;
        Bs2[lc + 0][lr] = dup2(vb0.x);          // dup at store time: 4 MOV/chunk
        Bs2[lc + 1][lr] = dup2(vb0.y);
        Bs2[lc + 2][lr] = dup2(vb0.z);
        Bs2[lc + 3][lr] = dup2(vb0.w);
        __syncthreads();

        if (k0 + BK < IN_DIM) {                 // prefetch under the FFMAs
            va0 = *reinterpret_cast<const float4*>(xp0 + k0 + BK);
            va1 = *reinterpret_cast<const float4*>(xp1 + k0 + BK);
            vb0 = *reinterpret_cast<const float4*>(wp0 + k0 + BK);
        }

#pragma unroll
        for (int kk = 0; kk < BK; kk++) {
            // 3x LDS.128, all broadcast-dedup (1 wavefront each); no MOVs.
            ulonglong2 av  = *reinterpret_cast<const ulonglong2*>(&As[kk][ty << 2]);
            ulonglong2 b01 = *reinterpret_cast<const ulonglong2*>(&Bs2[kk][tx << 2]);
            ulonglong2 b23 = *reinterpret_cast<const ulonglong2*>(&Bs2[kk][(tx << 2) + 2]);
            fma2(acc64[0], av.x, b01.x);  fma2(acc64[1], av.x, b01.y);
            fma2(acc64[2], av.x, b23.x);  fma2(acc64[3], av.x, b23.y);
            fma2(acc64[4], av.y, b01.x);  fma2(acc64[5], av.y, b01.y);
            fma2(acc64[6], av.y, b23.x);  fma2(acc64[7], av.y, b23.y);
        }
        __syncthreads();
    }

    float4 b4 = *reinterpret_cast<const float4*>(&bias[col0 + (tx << 2)]);
    const float bb[4] = {b4.x, b4.y, b4.z, b4.w};

    // ---------------- LIF recurrence (bit-exact) + packed mask write --------
#pragma unroll
    for (int i = 0; i < 4; i++) {
        float c0, c1, c2, c3;
        {
            const int p = (i >> 1) << 2;
            const int h = i & 1;
            float2 v0 = *reinterpret_cast<float2*>(&acc64[p + 0]);
            float2 v1 = *reinterpret_cast<float2*>(&acc64[p + 1]);
            float2 v2 = *reinterpret_cast<float2*>(&acc64[p + 2]);
            float2 v3 = *reinterpret_cast<float2*>(&acc64[p + 3]);
            c0 = (h ? v0.y : v0.x) + bb[0];
            c1 = (h ? v1.y : v1.x) + bb[1];
            c2 = (h ? v2.y : v2.x) + bb[2];
            c3 = (h ? v3.y : v3.x) + bb[3];
        }

        float m0 = 0.f, m1 = 0.f, m2 = 0.f, m3 = 0.f;
        bool  s0 = false, s1 = false, s2 = false, s3 = false;
        uint32_t lo0 = 0, lo1 = 0, lo2 = 0, lo3 = 0;
        uint32_t hi0 = 0, hi1 = 0, hi2 = 0, hi3 = 0;

#pragma unroll
        for (int t = 0; t < T50; t++) {
            float t0 = __fadd_rn(__fmul_rn(BETA, m0), c0);
            float t1 = __fadd_rn(__fmul_rn(BETA, m1), c1);
            float t2 = __fadd_rn(__fmul_rn(BETA, m2), c2);
            float t3 = __fadd_rn(__fmul_rn(BETA, m3), c3);
            m0 = s0 ? __fadd_rn(t0, -1.0f) : t0;
            m1 = s1 ? __fadd_rn(t1, -1.0f) : t1;
            m2 = s2 ? __fadd_rn(t2, -1.0f) : t2;
            m3 = s3 ? __fadd_rn(t3, -1.0f) : t3;
            s0 = m0 > 1.0f; s1 = m1 > 1.0f; s2 = m2 > 1.0f; s3 = m3 > 1.0f;
            if (t < 32) {
                lo0 |= s0 ? (1u << t) : 0u; lo1 |= s1 ? (1u << t) : 0u;
                lo2 |= s2 ? (1u << t) : 0u; lo3 |= s3 ? (1u << t) : 0u;
            } else {
                hi0 |= s0 ? (1u << (t - 32)) : 0u; hi1 |= s1 ? (1u << (t - 32)) : 0u;
                hi2 |= s2 ? (1u << (t - 32)) : 0u; hi3 |= s3 ? (1u << (t - 32)) : 0u;
            }
        }

        // 100-bit stream pack per 2-col group (verified rounds 6/7):
        //  w0=c0[0:32) w1=c0[32:50)|c1[0:14)<<18 w2=c1[14:46) w3=c1[46:50)
        const int r = (ty << 2) + i;
        {
            uint4 w;
            w.x = lo0;
            w.y = hi0 | (lo1 << 18);
            w.z = __funnelshift_r(lo1, hi1, 14);
            w.w = hi1 >> 14;
            *reinterpret_cast<uint4*>(&s_msk[((r << 4) + (tx << 1)) << 2]) = w;
            w.x = lo2;
            w.y = hi2 | (lo3 << 18);
            w.z = __funnelshift_r(lo3, hi3, 14);
            w.w = hi3 >> 14;
            *reinterpret_cast<uint4*>(&s_msk[((r << 4) + (tx << 1) + 1) << 2]) = w;
        }
    }
    __syncthreads();

    // ---------------- Expansion: 1 broadcast LDS.32 + shift-construct -------
    // Warp w owns rows [16w,16w+16). Lane L covers stream bits [4L,4L+4):
    // word = L>>3, shift = (4L)&31 (nibble never straddles a word).
    const int lane = tid & 31;
    const int warp = tid >> 5;

    if (lane < 25) {
        const int word = lane >> 3;
        const int shft = (lane << 2) & 31;
#pragma unroll
        for (int rr = 0; rr < 16; rr++) {
            int row = (warp << 4) + rr;
            const uint32_t* mrow = s_msk + (row << 6);      // 16 groups * 4 words
            float4* gout = reinterpret_cast<float4*>(
                out + (size_t)(row0 + row) * ROW_ELEMS + (size_t)col0 * T50) + lane;
#pragma unroll 4
            for (int cc = 0; cc < 16; cc++) {
                uint32_t w = mrow[(cc << 2) + word];        // broadcast LDS.32
                float4 v;
                v.x = __uint_as_float(((w >> (shft + 0)) & 1u) * 0x3f800000u);
                v.y = __uint_as_float(((w >> (shft + 1)) & 1u) * 0x3f800000u);
                v.z = __uint_as_float(((w >> (shft + 2)) & 1u) * 0x3f800000u);
                v.w = __uint_as_float(((w >> (shft + 3)) & 1u) * 0x3f800000u);
                __stcs(&gout[cc * 25], v);
            }
        }
    }
}

extern "C" void kernel_launch(void* const* d_in, const int* in_sizes, int n_in,
                              void* d_out, int out_size)
{
    const float* x    = (const float*)d_in[0];   // [8192, 512]
    const float* W    = (const float*)d_in[1];   // [256, 512]
    const float* bias = (const float*)d_in[2];   // [256]
    float*       out  = (float*)d_out;           // [8192, 256, 50]

    dim3 grid(OUT_DIM / TILE_N, B_DIM / TILE_M); // (8, 128) = 1024 blocks
    snn_fused7<<<grid, 128>>>(x, W, bias, out);
}

// round 13
// speedup vs baseline: 1.8081x; 1.8081x over previous
#include <cuda_runtime.h>
#include <stdint.h>

#define BETA      0.99f
#define T50       50
#define B_DIM     8192
#define IN_DIM    512
#define OUT_DIM   256

#define TILE_M    64          // batch rows per block
#define TILE_N    32          // output cols per block
#define BK        16
#define ROW_ELEMS (OUT_DIM * T50)   // 12800 floats per batch row

typedef unsigned long long ull;

__device__ __forceinline__ void fma2(ull& d, ull a, ull b) {
    asm("fma.rn.f32x2 %0, %1, %2, %0;" : "+l"(d) : "l"(a), "l"(b));
}
__device__ __forceinline__ ull dup2(float f) {
    ull r;
    asm("mov.b64 %0, {%1, %1};" : "=l"(r) : "f"(f));
    return r;
}

__global__ __launch_bounds__(128, 6) void snn_fused8(
    const float* __restrict__ x,     // [B_DIM, IN_DIM]
    const float* __restrict__ W,     // [OUT_DIM, IN_DIM]
    const float* __restrict__ bias,  // [OUT_DIM]
    float* __restrict__ out)         // [B_DIM, OUT_DIM, T50]
{
    __shared__ float As[BK][68];                // k-major, padded (R11 verbatim)
    __shared__ float Bs[BK][36];
    __shared__ uint32_t s_msk[TILE_M * 16 * 4]; // 16 KB packed 100-bit streams

    const int tid  = threadIdx.x;
    const int tx   = tid & 7;           // col group (4 cols each -> 32)
    const int ty   = tid >> 3;          // row group (4 rows each -> 64)
    const int col0 = blockIdx.x * TILE_N;
    const int row0 = blockIdx.y * TILE_M;

    // ---------------- GEMM: cur = x @ W^T + b  (R11 verbatim, 121us) --------
    ull acc64[8];
#pragma unroll
    for (int e = 0; e < 8; e++) acc64[e] = 0ull;

    const int lr = tid >> 2;            // 0..31
    const int lc = (tid & 3) << 2;      // 0,4,8,12
    const float* xp0 = x + (size_t)(row0 + lr) * IN_DIM + lc;
    const float* xp1 = xp0 + (size_t)32 * IN_DIM;
    const float* wp0 = W + (size_t)(col0 + lr) * IN_DIM + lc;

    float4 va0 = *reinterpret_cast<const float4*>(xp0);
    float4 va1 = *reinterpret_cast<const float4*>(xp1);
    float4 vb0 = *reinterpret_cast<const float4*>(wp0);

    for (int k0 = 0; k0 < IN_DIM; k0 += BK) {
        As[lc + 0][lr]      = va0.x; As[lc + 1][lr]      = va0.y;
        As[lc + 2][lr]      = va0.z; As[lc + 3][lr]      = va0.w;
        As[lc + 0][lr + 32] = va1.x; As[lc + 1][lr + 32] = va1.y;
        As[lc + 2][lr + 32] = va1.z; As[lc + 3][lr + 32] = va1.w;
        Bs[lc + 0][lr]      = vb0.x; Bs[lc + 1][lr]      = vb0.y;
        Bs[lc + 2][lr]      = vb0.z; Bs[lc + 3][lr]      = vb0.w;
        __syncthreads();

        if (k0 + BK < IN_DIM) {         // prefetch next chunk under the FFMAs
            va0 = *reinterpret_cast<const float4*>(xp0 + k0 + BK);
            va1 = *reinterpret_cast<const float4*>(xp1 + k0 + BK);
            vb0 = *reinterpret_cast<const float4*>(wp0 + k0 + BK);
        }

#pragma unroll
        for (int kk = 0; kk < BK; kk++) {
            // 2x conflict-free LDS.128 + 4 MOV dup + 8 FFMA2 (R11 verbatim)
            ulonglong2 av = *reinterpret_cast<const ulonglong2*>(&As[kk][ty << 2]);
            float4 b  = *reinterpret_cast<const float4*>(&Bs[kk][tx << 2]);
            ull b0 = dup2(b.x), b1 = dup2(b.y), b2 = dup2(b.z), b3 = dup2(b.w);
            fma2(acc64[0], av.x, b0);  fma2(acc64[1], av.x, b1);
            fma2(acc64[2], av.x, b2);  fma2(acc64[3], av.x, b3);
            fma2(acc64[4], av.y, b0);  fma2(acc64[5], av.y, b1);
            fma2(acc64[6], av.y, b2);  fma2(acc64[7], av.y, b3);
        }
        __syncthreads();
    }

    float4 b4 = *reinterpret_cast<const float4*>(&bias[col0 + (tx << 2)]);
    const float bb[4] = {b4.x, b4.y, b4.z, b4.w};

    // ---------------- LIF recurrence (bit-exact) + packed mask write --------
#pragma unroll
    for (int i = 0; i < 4; i++) {
        float c0, c1, c2, c3;
        {
            const int p = (i >> 1) << 2;
            const int h = i & 1;
            float2 v0 = *reinterpret_cast<float2*>(&acc64[p + 0]);
            float2 v1 = *reinterpret_cast<float2*>(&acc64[p + 1]);
            float2 v2 = *reinterpret_cast<float2*>(&acc64[p + 2]);
            float2 v3 = *reinterpret_cast<float2*>(&acc64[p + 3]);
            c0 = (h ? v0.y : v0.x) + bb[0];
            c1 = (h ? v1.y : v1.x) + bb[1];
            c2 = (h ? v2.y : v2.x) + bb[2];
            c3 = (h ? v3.y : v3.x) + bb[3];
        }

        float m0 = 0.f, m1 = 0.f, m2 = 0.f, m3 = 0.f;
        bool  s0 = false, s1 = false, s2 = false, s3 = false;
        uint32_t lo0 = 0, lo1 = 0, lo2 = 0, lo3 = 0;
        uint32_t hi0 = 0, hi1 = 0, hi2 = 0, hi3 = 0;

#pragma unroll
        for (int t = 0; t < T50; t++) {
            float t0 = __fadd_rn(__fmul_rn(BETA, m0), c0);
            float t1 = __fadd_rn(__fmul_rn(BETA, m1), c1);
            float t2 = __fadd_rn(__fmul_rn(BETA, m2), c2);
            float t3 = __fadd_rn(__fmul_rn(BETA, m3), c3);
            m0 = s0 ? __fadd_rn(t0, -1.0f) : t0;
            m1 = s1 ? __fadd_rn(t1, -1.0f) : t1;
            m2 = s2 ? __fadd_rn(t2, -1.0f) : t2;
            m3 = s3 ? __fadd_rn(t3, -1.0f) : t3;
            s0 = m0 > 1.0f; s1 = m1 > 1.0f; s2 = m2 > 1.0f; s3 = m3 > 1.0f;
            if (t < 32) {
                lo0 |= s0 ? (1u << t) : 0u; lo1 |= s1 ? (1u << t) : 0u;
                lo2 |= s2 ? (1u << t) : 0u; lo3 |= s3 ? (1u << t) : 0u;
            } else {
                hi0 |= s0 ? (1u << (t - 32)) : 0u; hi1 |= s1 ? (1u << (t - 32)) : 0u;
                hi2 |= s2 ? (1u << (t - 32)) : 0u; hi3 |= s3 ? (1u << (t - 32)) : 0u;
            }
        }

        // 100-bit stream pack per 2-col group (verified rounds 6/7/12):
        //  w0=c0[0:32) w1=c0[32:50)|c1[0:14)<<18 w2=c1[14:46) w3=c1[46:50)
        const int r = (ty << 2) + i;
        {
            uint4 w;
            w.x = lo0;
            w.y = hi0 | (lo1 << 18);
            w.z = __funnelshift_r(lo1, hi1, 14);
            w.w = hi1 >> 14;
            *reinterpret_cast<uint4*>(&s_msk[((r << 4) + (tx << 1)) << 2]) = w;
            w.x = lo2;
            w.y = hi2 | (lo3 << 18);
            w.z = __funnelshift_r(lo3, hi3, 14);
            w.w = hi3 >> 14;
            *reinterpret_cast<uint4*>(&s_msk[((r << 4) + (tx << 1) + 1) << 2]) = w;
        }
    }
    __syncthreads();

    // ---------------- Expansion: 1 broadcast LDS.32 + shift-construct -------
    // Warp w owns rows [16w,16w+16). Lane L covers stream bits [4L,4L+4):
    // word = L>>3, shift = (4L)&31 (nibble never straddles a word; 8 lanes
    // share each word -> single broadcast wavefront).
    const int lane = tid & 31;
    const int warp = tid >> 5;

    if (lane < 25) {
        const int word = lane >> 3;
        const int shft = (lane << 2) & 31;
#pragma unroll
        for (int rr = 0; rr < 16; rr++) {
            int row = (warp << 4) + rr;
            const uint32_t* mrow = s_msk + (row << 6);      // 16 groups * 4 words
            float4* gout = reinterpret_cast<float4*>(
                out + (size_t)(row0 + row) * ROW_ELEMS + (size_t)col0 * T50) + lane;
#pragma unroll 4
            for (int cc = 0; cc < 16; cc++) {
                uint32_t w = mrow[(cc << 2) + word];        // broadcast LDS.32
                float4 v;
                v.x = __uint_as_float(((w >> (shft + 0)) & 1u) * 0x3f800000u);
                v.y = __uint_as_float(((w >> (shft + 1)) & 1u) * 0x3f800000u);
                v.z = __uint_as_float(((w >> (shft + 2)) & 1u) * 0x3f800000u);
                v.w = __uint_as_float(((w >> (shft + 3)) & 1u) * 0x3f800000u);
                __stcs(&gout[cc * 25], v);
            }
        }
    }
}

extern "C" void kernel_launch(void* const* d_in, const int* in_sizes, int n_in,
                              void* d_out, int out_size)
{
    const float* x    = (const float*)d_in[0];   // [8192, 512]
    const float* W    = (const float*)d_in[1];   // [256, 512]
    const float* bias = (const float*)d_in[2];   // [256]
    float*       out  = (float*)d_out;           // [8192, 256, 50]

    dim3 grid(OUT_DIM / TILE_N, B_DIM / TILE_M); // (8, 128) = 1024 blocks
    snn_fused8<<<grid, 128>>>(x, W, bias, out);
}